// round 10
// baseline (speedup 1.0000x reference)
#include <cuda_runtime.h>
#include <cstdint>
#include <math.h>

// ---------------------------------------------------------------------------
// Problem shape
// ---------------------------------------------------------------------------
constexpr int L = 4096;     // queries
constexpr int D = 2048;     // head dim
constexpr int T = 4096;     // kv tokens
constexpr int WIN = 1024;   // sliding window

// GEMM tiling
constexpr int BM = 128, BN = 128, BK = 32;
constexpr int STAGES = 4;
constexpr int LDSW = 36;                      // smem row stride in floats (conflict-free)
constexpr int A_FLOATS = BM * LDSW;           // 4608 floats per A tile
constexpr int STAGE_FLOATS = 2 * A_FLOATS;    // 9216 (A + B)
constexpr int GSMEM_BYTES = STAGES * STAGE_FLOATS * 4;  // 147456

// Band tile helpers (128-wide column tiles) for query row-block bi
__host__ __device__ __forceinline__ int band_j0(int bi) { int j = bi - 8; return j < 0 ? 0 : j; }
__host__ __device__ __forceinline__ int band_j1(int bi) { int j = bi + 9; return j > T / 128 ? T / 128 : j; }

// ---------------------------------------------------------------------------
// Scratch (device globals; allocation-free)
// ---------------------------------------------------------------------------
__device__ float g_xr[(size_t)L * D];   // x rounded to tf32
__device__ float g_wr[(size_t)D * D];   // Wq rounded
__device__ float g_kr[(size_t)T * D];   // Pk rounded
__device__ float g_vt[(size_t)D * T];   // Pv transposed + rounded
__device__ float g_Q [(size_t)L * D];   // Q (tf32-rounded in epilogue)
__device__ float g_S [(size_t)L * T];   // scores -> probs (rounded)

// ---------------------------------------------------------------------------
// PTX helpers (baseline compute_103 features only)
// ---------------------------------------------------------------------------
__device__ __forceinline__ uint32_t smem_u32(const void* p) {
    uint32_t a;
    asm("{ .reg .u64 t; cvta.to.shared.u64 t, %1; cvt.u32.u64 %0, t; }" : "=r"(a) : "l"(p));
    return a;
}
__device__ __forceinline__ float rna_tf32(float x) {
    uint32_t r;
    asm("cvt.rna.tf32.f32 %0, %1;" : "=r"(r) : "f"(x));
    return __uint_as_float(r);
}
__device__ __forceinline__ void cp_async16(uint32_t dst, const void* src) {
    asm volatile("cp.async.cg.shared.global [%0], [%1], 16;" :: "r"(dst), "l"(src));
}
#define CP_COMMIT() asm volatile("cp.async.commit_group;" ::: "memory")
#define CP_WAIT(n)  asm volatile("cp.async.wait_group %0;" :: "n"(n) : "memory")

__device__ __forceinline__ void mma_tf32(float* c, const uint32_t* a, const uint32_t* b) {
    asm volatile("mma.sync.aligned.m16n8k8.row.col.f32.tf32.tf32.f32 "
        "{%0,%1,%2,%3}, {%4,%5,%6,%7}, {%8,%9}, {%0,%1,%2,%3};"
        : "+f"(c[0]), "+f"(c[1]), "+f"(c[2]), "+f"(c[3])
        : "r"(a[0]), "r"(a[1]), "r"(a[2]), "r"(a[3]), "r"(b[0]), "r"(b[1]));
}

// ---------------------------------------------------------------------------
// GEMM body: C[BM x BN] tile at (m0, n0) = alpha * A(MxK) @ B^T (B is NxK),
// K in [kStart, kEnd). A, B row-major K-contiguous. 256 threads.
// ---------------------------------------------------------------------------
template <bool ROUND>
__device__ __forceinline__ void gemm_body(
    const float* __restrict__ A, const float* __restrict__ B, float* __restrict__ C,
    int lda, int ldb, int ldc, int m0, int n0, int kStart, int kEnd, float alpha)
{
    extern __shared__ float smem[];
    const uint32_t sb = smem_u32(smem);
    const int tid = threadIdx.x;
    const int lane = tid & 31, wid = tid >> 5;
    const int warp_m = wid & 3, warp_n = wid >> 2;   // 4 x 2 warp grid
    const int g = lane >> 2, tg = lane & 3;           // groupID, thread-in-group

    const int NK = (kEnd - kStart) >> 5;

    // issue one stage of cp.async loads (A tile 128x32, B tile 128x32)
    auto load_stage = [&](int s, int k0) {
        uint32_t base = sb + (uint32_t)(s * STAGE_FLOATS * 4);
#pragma unroll
        for (int i = 0; i < 4; i++) {
            int id = tid + i * 256;           // 0..1023
            int row = id >> 3, c = id & 7;
            cp_async16(base + row * (LDSW * 4) + c * 16,
                       A + (size_t)(m0 + row) * lda + k0 + c * 4);
        }
        base += A_FLOATS * 4;
#pragma unroll
        for (int i = 0; i < 4; i++) {
            int id = tid + i * 256;
            int row = id >> 3, c = id & 7;
            cp_async16(base + row * (LDSW * 4) + c * 16,
                       B + (size_t)(n0 + row) * ldb + k0 + c * 4);
        }
    };

    float acc[2][8][4];
#pragma unroll
    for (int mf = 0; mf < 2; mf++)
#pragma unroll
        for (int nf = 0; nf < 8; nf++)
#pragma unroll
            for (int q = 0; q < 4; q++) acc[mf][nf][q] = 0.0f;

    // prologue
#pragma unroll
    for (int s = 0; s < STAGES - 1; s++) {
        if (s < NK) load_stage(s, kStart + s * BK);
        CP_COMMIT();
    }
    CP_WAIT(STAGES - 2);
    __syncthreads();

    for (int c = 0; c < NK; c++) {
        int nxt = c + STAGES - 1;
        if (nxt < NK) load_stage(nxt & (STAGES - 1), kStart + nxt * BK);
        CP_COMMIT();

        const uint32_t* As = (const uint32_t*)smem + (c & (STAGES - 1)) * STAGE_FLOATS;
        const uint32_t* Bs = As + A_FLOATS;
        const uint32_t* pa = As + (warp_m * 32 + g) * LDSW + tg;
        const uint32_t* pb = Bs + (warp_n * 64 + g) * LDSW + tg;

#pragma unroll
        for (int kk = 0; kk < 4; kk++) {
            uint32_t a[2][4], b[8][2];
#pragma unroll
            for (int mf = 0; mf < 2; mf++) {
                const uint32_t* p = pa + mf * 16 * LDSW + kk * 8;
                a[mf][0] = p[0];
                a[mf][1] = p[8 * LDSW];
                a[mf][2] = p[4];
                a[mf][3] = p[8 * LDSW + 4];
            }
#pragma unroll
            for (int nf = 0; nf < 8; nf++) {
                const uint32_t* p = pb + nf * 8 * LDSW + kk * 8;
                b[nf][0] = p[0];
                b[nf][1] = p[4];
            }
#pragma unroll
            for (int mf = 0; mf < 2; mf++)
#pragma unroll
                for (int nf = 0; nf < 8; nf++)
                    mma_tf32(acc[mf][nf], a[mf], b[nf]);
        }

        CP_WAIT(STAGES - 2);
        __syncthreads();
    }

    // epilogue: c0:(g, 2tg) c1:(g, 2tg+1) c2:(g+8, 2tg) c3:(g+8, 2tg+1)
    const int row0 = m0 + warp_m * 32;
    const int col0 = n0 + warp_n * 64;
#pragma unroll
    for (int mf = 0; mf < 2; mf++) {
#pragma unroll
        for (int nf = 0; nf < 8; nf++) {
            int r = row0 + mf * 16 + g;
            int cc = col0 + nf * 8 + 2 * tg;
            float2 v0, v1;
            v0.x = alpha * acc[mf][nf][0];
            v0.y = alpha * acc[mf][nf][1];
            v1.x = alpha * acc[mf][nf][2];
            v1.y = alpha * acc[mf][nf][3];
            if (ROUND) {
                v0.x = rna_tf32(v0.x); v0.y = rna_tf32(v0.y);
                v1.x = rna_tf32(v1.x); v1.y = rna_tf32(v1.y);
            }
            *(float2*)&C[(size_t)r * ldc + cc] = v0;
            *(float2*)&C[(size_t)(r + 8) * ldc + cc] = v1;
        }
    }
}

// ---------------------------------------------------------------------------
// Kernels
// ---------------------------------------------------------------------------
__global__ __launch_bounds__(256, 1) void qgemm_kernel(const float* __restrict__ xr,
                                                       const float* __restrict__ wr)
{
    gemm_body<true>(xr, wr, g_Q, D, D, D, blockIdx.y * BM, blockIdx.x * BN, 0, D, 1.0f);
}

__global__ __launch_bounds__(256, 1) void sgemm_kernel(const float* __restrict__ kr, float scale)
{
    int bi = blockIdx.y;
    int bj = band_j0(bi) + (int)blockIdx.x;
    if (bj >= band_j1(bi)) return;
    gemm_body<false>(g_Q, kr, g_S, D, D, T, bi * BM, bj * BN, 0, D, scale);
}

__global__ __launch_bounds__(256, 1) void pvgemm_kernel(const float* __restrict__ vt,
                                                        float* __restrict__ out)
{
    int bi = blockIdx.y;
    gemm_body<false>(g_S, vt, out, T, T, D, bi * BM, blockIdx.x * BN,
                     band_j0(bi) * 128, band_j1(bi) * 128, 1.0f);
}

// Elementwise round-to-nearest tf32 (float4 grid-stride)
__global__ void round_kernel(const float4* __restrict__ in, float4* __restrict__ out, int n4)
{
    for (int i = blockIdx.x * blockDim.x + threadIdx.x; i < n4; i += gridDim.x * blockDim.x) {
        float4 v = in[i];
        v.x = rna_tf32(v.x); v.y = rna_tf32(v.y); v.z = rna_tf32(v.z); v.w = rna_tf32(v.w);
        out[i] = v;
    }
}

// Pv (T x D) -> PvT (D x T), rounded
__global__ void transpose_round_kernel(const float* __restrict__ in, float* __restrict__ out)
{
    __shared__ float tile[32][33];
    int x = blockIdx.x * 32 + threadIdx.x;   // d index
    int y = blockIdx.y * 32 + threadIdx.y;   // token index
#pragma unroll
    for (int j = 0; j < 32; j += 8)
        tile[threadIdx.y + j][threadIdx.x] = in[(size_t)(y + j) * D + x];
    __syncthreads();
    int xo = blockIdx.y * 32 + threadIdx.x;  // token index in out
    int yo = blockIdx.x * 32 + threadIdx.y;  // d index
#pragma unroll
    for (int j = 0; j < 32; j += 8)
        out[(size_t)(yo + j) * T + xo] = rna_tf32(tile[threadIdx.x][threadIdx.y + j]);
}

// Row softmax on the sliding-window band; writes tf32-rounded probs and
// zero-fills the 128-tile band region outside the exact window.
__global__ __launch_bounds__(256) void softmax_kernel()
{
    const int i = blockIdx.x;
    const int tid = threadIdx.x;
    float* srow = &g_S[(size_t)i * T];

    const int lo = max(0, i - (WIN - 1));
    const int hi = min(T - 1, i + (WIN - 1));
    const int bi = i >> 7;
    const int c0 = band_j0(bi) * 128;
    const int c1 = band_j1(bi) * 128;

    __shared__ float red[256];

    float m = -INFINITY;
    for (int t = lo + tid; t <= hi; t += 256) m = fmaxf(m, srow[t]);
    red[tid] = m;
    __syncthreads();
    for (int s = 128; s > 0; s >>= 1) { if (tid < s) red[tid] = fmaxf(red[tid], red[tid + s]); __syncthreads(); }
    const float rowMax = red[0];
    __syncthreads();

    float sum = 0.0f;
    for (int t = lo + tid; t <= hi; t += 256) sum += expf(srow[t] - rowMax);
    red[tid] = sum;
    __syncthreads();
    for (int s = 128; s > 0; s >>= 1) { if (tid < s) red[tid] += red[tid + s]; __syncthreads(); }
    const float inv = 1.0f / red[0];
    __syncthreads();

    for (int t = c0 + tid; t < c1; t += 256) {
        float v = 0.0f;
        if (t >= lo && t <= hi) v = rna_tf32(expf(srow[t] - rowMax) * inv);
        srow[t] = v;
    }
}

// ---------------------------------------------------------------------------
// Host
// ---------------------------------------------------------------------------
extern "C" void kernel_launch(void* const* d_in, const int* in_sizes, int n_in,
                              void* d_out, int out_size)
{
    const float* x  = (const float*)d_in[0];
    const float* Wq = (const float*)d_in[1];
    const float* Pk = (const float*)d_in[2];
    const float* Pv = (const float*)d_in[3];
    float* out = (float*)d_out;

    void *pxr, *pwr, *pkr, *pvt;
    cudaGetSymbolAddress(&pxr, g_xr);
    cudaGetSymbolAddress(&pwr, g_wr);
    cudaGetSymbolAddress(&pkr, g_kr);
    cudaGetSymbolAddress(&pvt, g_vt);

    cudaFuncSetAttribute(qgemm_kernel,  cudaFuncAttributeMaxDynamicSharedMemorySize, GSMEM_BYTES);
    cudaFuncSetAttribute(sgemm_kernel,  cudaFuncAttributeMaxDynamicSharedMemorySize, GSMEM_BYTES);
    cudaFuncSetAttribute(pvgemm_kernel, cudaFuncAttributeMaxDynamicSharedMemorySize, GSMEM_BYTES);

    const float scale = 0.022097086912079612f;  // 1/sqrt(2048)

    // RN-round inputs to tf32
    round_kernel<<<2048, 256>>>((const float4*)x,  (float4*)pxr, (L * D) / 4);
    round_kernel<<<2048, 256>>>((const float4*)Wq, (float4*)pwr, (D * D) / 4);
    round_kernel<<<2048, 256>>>((const float4*)Pk, (float4*)pkr, (T * D) / 4);
    transpose_round_kernel<<<dim3(D / 32, T / 32), dim3(32, 8)>>>(Pv, (float*)pvt);

    // Q = x @ Wq^T
    qgemm_kernel<<<dim3(D / BN, L / BM), 256, GSMEM_BYTES>>>((const float*)pxr, (const float*)pwr);
    // S = scale * Q @ Pk^T (banded column tiles)
    sgemm_kernel<<<dim3(17, L / BM), 256, GSMEM_BYTES>>>((const float*)pkr, scale);
    // banded softmax -> probs
    softmax_kernel<<<L, 256>>>();
    // Y = probs @ Pv (banded K range)
    pvgemm_kernel<<<dim3(D / BN, L / BM), 256, GSMEM_BYTES>>>((const float*)pvt, out);
}

// round 11
// speedup vs baseline: 1.0020x; 1.0020x over previous
#include <cuda_runtime.h>
#include <cstdint>
#include <math.h>

// ---------------------------------------------------------------------------
// Problem shape
// ---------------------------------------------------------------------------
constexpr int L = 4096;     // queries
constexpr int D = 2048;     // head dim
constexpr int T = 4096;     // kv tokens
constexpr int WIN = 1024;   // sliding window

// GEMM tiling
constexpr int BM = 128, BN = 128, BK = 32;
constexpr int STAGES = 4;
constexpr int LDSW = 36;                      // smem row stride in floats (conflict-free)
constexpr int A_FLOATS = BM * LDSW;           // 4608 floats per A tile
constexpr int STAGE_FLOATS = 2 * A_FLOATS;    // 9216 (A + B)
constexpr int GSMEM_BYTES = STAGES * STAGE_FLOATS * 4;  // 147456

// Band tile helpers (128-wide column tiles) for query row-block bi
__host__ __device__ __forceinline__ int band_j0(int bi) { int j = bi - 8; return j < 0 ? 0 : j; }
__host__ __device__ __forceinline__ int band_j1(int bi) { int j = bi + 9; return j > T / 128 ? T / 128 : j; }

// ---------------------------------------------------------------------------
// Scratch (device globals; allocation-free)
// ---------------------------------------------------------------------------
__device__ float g_xr[(size_t)L * D];   // x rounded to tf32
__device__ float g_wr[(size_t)D * D];   // Wq rounded
__device__ float g_kr[(size_t)T * D];   // Pk rounded
__device__ float g_vt[(size_t)D * T];   // Pv transposed + rounded
__device__ float g_Q [(size_t)L * D];   // Q (tf32-rounded in epilogue)
__device__ float g_S [(size_t)L * T];   // scores -> probs (rounded)

// ---------------------------------------------------------------------------
// PTX helpers (baseline compute_103 features only)
// ---------------------------------------------------------------------------
__device__ __forceinline__ uint32_t smem_u32(const void* p) {
    uint32_t a;
    asm("{ .reg .u64 t; cvta.to.shared.u64 t, %1; cvt.u32.u64 %0, t; }" : "=r"(a) : "l"(p));
    return a;
}
__device__ __forceinline__ float rna_tf32(float x) {
    uint32_t r;
    asm("cvt.rna.tf32.f32 %0, %1;" : "=r"(r) : "f"(x));
    return __uint_as_float(r);
}
__device__ __forceinline__ void cp_async16(uint32_t dst, const void* src) {
    asm volatile("cp.async.cg.shared.global [%0], [%1], 16;" :: "r"(dst), "l"(src));
}
#define CP_COMMIT() asm volatile("cp.async.commit_group;" ::: "memory")
#define CP_WAIT(n)  asm volatile("cp.async.wait_group %0;" :: "n"(n) : "memory")

__device__ __forceinline__ void mma_tf32(float* c, const uint32_t* a, const uint32_t* b) {
    asm volatile("mma.sync.aligned.m16n8k8.row.col.f32.tf32.tf32.f32 "
        "{%0,%1,%2,%3}, {%4,%5,%6,%7}, {%8,%9}, {%0,%1,%2,%3};"
        : "+f"(c[0]), "+f"(c[1]), "+f"(c[2]), "+f"(c[3])
        : "r"(a[0]), "r"(a[1]), "r"(a[2]), "r"(a[3]), "r"(b[0]), "r"(b[1]));
}

// ---------------------------------------------------------------------------
// GEMM body: C[BM x BN] tile at (m0, n0) = alpha * A(MxK) @ B^T (B is NxK),
// K in [kStart, kEnd). A, B row-major K-contiguous. 256 threads.
// ---------------------------------------------------------------------------
template <bool ROUND>
__device__ __forceinline__ void gemm_body(
    const float* __restrict__ A, const float* __restrict__ B, float* __restrict__ C,
    int lda, int ldb, int ldc, int m0, int n0, int kStart, int kEnd, float alpha)
{
    extern __shared__ float smem[];
    const uint32_t sb = smem_u32(smem);
    const int tid = threadIdx.x;
    const int lane = tid & 31, wid = tid >> 5;
    const int warp_m = wid & 3, warp_n = wid >> 2;   // 4 x 2 warp grid
    const int g = lane >> 2, tg = lane & 3;           // groupID, thread-in-group

    const int NK = (kEnd - kStart) >> 5;

    // issue one stage of cp.async loads (A tile 128x32, B tile 128x32)
    auto load_stage = [&](int s, int k0) {
        uint32_t base = sb + (uint32_t)(s * STAGE_FLOATS * 4);
#pragma unroll
        for (int i = 0; i < 4; i++) {
            int id = tid + i * 256;           // 0..1023
            int row = id >> 3, c = id & 7;
            cp_async16(base + row * (LDSW * 4) + c * 16,
                       A + (size_t)(m0 + row) * lda + k0 + c * 4);
        }
        base += A_FLOATS * 4;
#pragma unroll
        for (int i = 0; i < 4; i++) {
            int id = tid + i * 256;
            int row = id >> 3, c = id & 7;
            cp_async16(base + row * (LDSW * 4) + c * 16,
                       B + (size_t)(n0 + row) * ldb + k0 + c * 4);
        }
    };

    float acc[2][8][4];
#pragma unroll
    for (int mf = 0; mf < 2; mf++)
#pragma unroll
        for (int nf = 0; nf < 8; nf++)
#pragma unroll
            for (int q = 0; q < 4; q++) acc[mf][nf][q] = 0.0f;

    // prologue
#pragma unroll
    for (int s = 0; s < STAGES - 1; s++) {
        if (s < NK) load_stage(s, kStart + s * BK);
        CP_COMMIT();
    }
    CP_WAIT(STAGES - 2);
    __syncthreads();

    for (int c = 0; c < NK; c++) {
        int nxt = c + STAGES - 1;
        if (nxt < NK) load_stage(nxt & (STAGES - 1), kStart + nxt * BK);
        CP_COMMIT();

        const uint32_t* As = (const uint32_t*)smem + (c & (STAGES - 1)) * STAGE_FLOATS;
        const uint32_t* Bs = As + A_FLOATS;
        const uint32_t* pa = As + (warp_m * 32 + g) * LDSW + tg;
        const uint32_t* pb = Bs + (warp_n * 64 + g) * LDSW + tg;

#pragma unroll
        for (int kk = 0; kk < 4; kk++) {
            uint32_t a[2][4], b[8][2];
#pragma unroll
            for (int mf = 0; mf < 2; mf++) {
                const uint32_t* p = pa + mf * 16 * LDSW + kk * 8;
                a[mf][0] = p[0];
                a[mf][1] = p[8 * LDSW];
                a[mf][2] = p[4];
                a[mf][3] = p[8 * LDSW + 4];
            }
#pragma unroll
            for (int nf = 0; nf < 8; nf++) {
                const uint32_t* p = pb + nf * 8 * LDSW + kk * 8;
                b[nf][0] = p[0];
                b[nf][1] = p[4];
            }
#pragma unroll
            for (int mf = 0; mf < 2; mf++)
#pragma unroll
                for (int nf = 0; nf < 8; nf++)
                    mma_tf32(acc[mf][nf], a[mf], b[nf]);
        }

        CP_WAIT(STAGES - 2);
        __syncthreads();
    }

    // epilogue: c0:(g, 2tg) c1:(g, 2tg+1) c2:(g+8, 2tg) c3:(g+8, 2tg+1)
    const int row0 = m0 + warp_m * 32;
    const int col0 = n0 + warp_n * 64;
#pragma unroll
    for (int mf = 0; mf < 2; mf++) {
#pragma unroll
        for (int nf = 0; nf < 8; nf++) {
            int r = row0 + mf * 16 + g;
            int cc = col0 + nf * 8 + 2 * tg;
            float2 v0, v1;
            v0.x = alpha * acc[mf][nf][0];
            v0.y = alpha * acc[mf][nf][1];
            v1.x = alpha * acc[mf][nf][2];
            v1.y = alpha * acc[mf][nf][3];
            if (ROUND) {
                v0.x = rna_tf32(v0.x); v0.y = rna_tf32(v0.y);
                v1.x = rna_tf32(v1.x); v1.y = rna_tf32(v1.y);
            }
            *(float2*)&C[(size_t)r * ldc + cc] = v0;
            *(float2*)&C[(size_t)(r + 8) * ldc + cc] = v1;
        }
    }
}

// ---------------------------------------------------------------------------
// Kernels
// ---------------------------------------------------------------------------
__global__ __launch_bounds__(256, 1) void qgemm_kernel(const float* __restrict__ xr,
                                                       const float* __restrict__ wr)
{
    gemm_body<true>(xr, wr, g_Q, D, D, D, blockIdx.y * BM, blockIdx.x * BN, 0, D, 1.0f);
}

__global__ __launch_bounds__(256, 1) void sgemm_kernel(const float* __restrict__ kr, float scale)
{
    int bi = blockIdx.y;
    int bj = band_j0(bi) + (int)blockIdx.x;
    if (bj >= band_j1(bi)) return;
    gemm_body<false>(g_Q, kr, g_S, D, D, T, bi * BM, bj * BN, 0, D, scale);
}

__global__ __launch_bounds__(256, 1) void pvgemm_kernel(const float* __restrict__ vt,
                                                        float* __restrict__ out)
{
    int bi = blockIdx.y;
    gemm_body<false>(g_S, vt, out, T, T, D, bi * BM, blockIdx.x * BN,
                     band_j0(bi) * 128, band_j1(bi) * 128, 1.0f);
}

// Elementwise round-to-nearest tf32 (float4 grid-stride)
__global__ void round_kernel(const float4* __restrict__ in, float4* __restrict__ out, int n4)
{
    for (int i = blockIdx.x * blockDim.x + threadIdx.x; i < n4; i += gridDim.x * blockDim.x) {
        float4 v = in[i];
        v.x = rna_tf32(v.x); v.y = rna_tf32(v.y); v.z = rna_tf32(v.z); v.w = rna_tf32(v.w);
        out[i] = v;
    }
}

// Pv (T x D) -> PvT (D x T), rounded
__global__ void transpose_round_kernel(const float* __restrict__ in, float* __restrict__ out)
{
    __shared__ float tile[32][33];
    int x = blockIdx.x * 32 + threadIdx.x;   // d index
    int y = blockIdx.y * 32 + threadIdx.y;   // token index
#pragma unroll
    for (int j = 0; j < 32; j += 8)
        tile[threadIdx.y + j][threadIdx.x] = in[(size_t)(y + j) * D + x];
    __syncthreads();
    int xo = blockIdx.y * 32 + threadIdx.x;  // token index in out
    int yo = blockIdx.x * 32 + threadIdx.y;  // d index
#pragma unroll
    for (int j = 0; j < 32; j += 8)
        out[(size_t)(yo + j) * T + xo] = rna_tf32(tile[threadIdx.x][threadIdx.y + j]);
}

// Row softmax on the sliding-window band; writes tf32-rounded probs and
// zero-fills the 128-tile band region outside the exact window.
__global__ __launch_bounds__(256) void softmax_kernel()
{
    const int i = blockIdx.x;
    const int tid = threadIdx.x;
    float* srow = &g_S[(size_t)i * T];

    const int lo = max(0, i - (WIN - 1));
    const int hi = min(T - 1, i + (WIN - 1));
    const int bi = i >> 7;
    const int c0 = band_j0(bi) * 128;
    const int c1 = band_j1(bi) * 128;

    __shared__ float red[256];

    float m = -INFINITY;
    for (int t = lo + tid; t <= hi; t += 256) m = fmaxf(m, srow[t]);
    red[tid] = m;
    __syncthreads();
    for (int s = 128; s > 0; s >>= 1) { if (tid < s) red[tid] = fmaxf(red[tid], red[tid + s]); __syncthreads(); }
    const float rowMax = red[0];
    __syncthreads();

    float sum = 0.0f;
    for (int t = lo + tid; t <= hi; t += 256) sum += expf(srow[t] - rowMax);
    red[tid] = sum;
    __syncthreads();
    for (int s = 128; s > 0; s >>= 1) { if (tid < s) red[tid] += red[tid + s]; __syncthreads(); }
    const float inv = 1.0f / red[0];
    __syncthreads();

    for (int t = c0 + tid; t < c1; t += 256) {
        float v = 0.0f;
        if (t >= lo && t <= hi) v = rna_tf32(expf(srow[t] - rowMax) * inv);
        srow[t] = v;
    }
}

// ---------------------------------------------------------------------------
// Host
// ---------------------------------------------------------------------------
extern "C" void kernel_launch(void* const* d_in, const int* in_sizes, int n_in,
                              void* d_out, int out_size)
{
    const float* x  = (const float*)d_in[0];
    const float* Wq = (const float*)d_in[1];
    const float* Pk = (const float*)d_in[2];
    const float* Pv = (const float*)d_in[3];
    float* out = (float*)d_out;

    void *pxr, *pwr, *pkr, *pvt;
    cudaGetSymbolAddress(&pxr, g_xr);
    cudaGetSymbolAddress(&pwr, g_wr);
    cudaGetSymbolAddress(&pkr, g_kr);
    cudaGetSymbolAddress(&pvt, g_vt);

    cudaFuncSetAttribute(qgemm_kernel,  cudaFuncAttributeMaxDynamicSharedMemorySize, GSMEM_BYTES);
    cudaFuncSetAttribute(sgemm_kernel,  cudaFuncAttributeMaxDynamicSharedMemorySize, GSMEM_BYTES);
    cudaFuncSetAttribute(pvgemm_kernel, cudaFuncAttributeMaxDynamicSharedMemorySize, GSMEM_BYTES);

    const float scale = 0.022097086912079612f;  // 1/sqrt(2048)

    // RN-round inputs to tf32
    round_kernel<<<2048, 256>>>((const float4*)x,  (float4*)pxr, (L * D) / 4);
    round_kernel<<<2048, 256>>>((const float4*)Wq, (float4*)pwr, (D * D) / 4);
    round_kernel<<<2048, 256>>>((const float4*)Pk, (float4*)pkr, (T * D) / 4);
    transpose_round_kernel<<<dim3(D / 32, T / 32), dim3(32, 8)>>>(Pv, (float*)pvt);

    // Q = x @ Wq^T
    qgemm_kernel<<<dim3(D / BN, L / BM), 256, GSMEM_BYTES>>>((const float*)pxr, (const float*)pwr);
    // S = scale * Q @ Pk^T (banded column tiles)
    sgemm_kernel<<<dim3(17, L / BM), 256, GSMEM_BYTES>>>((const float*)pkr, scale);
    // banded softmax -> probs
    softmax_kernel<<<L, 256>>>();
    // Y = probs @ Pv (banded K range)
    pvgemm_kernel<<<dim3(D / BN, L / BM), 256, GSMEM_BYTES>>>((const float*)pvt, out);
}